// round 12
// baseline (speedup 1.0000x reference)
#include <cuda_runtime.h>
#include <cuda_fp16.h>
#include <math.h>
#include <stdint.h>

#define BB 2
#define TT 2048
#define DMODEL 1024
#define NH 16
#define DK 64
#define MROWS (BB * TT)   // 4096

// ---- scratch (static device memory; no allocations allowed) ----
__device__ __half g_xh[(size_t)MROWS * DMODEL];      // x  -> fp16
__device__ __half g_wqh[(size_t)DMODEL * DMODEL];    // Wq -> fp16
__device__ __half g_wkh[(size_t)DMODEL * DMODEL];
__device__ __half g_wvh[(size_t)DMODEL * DMODEL];
__device__ __half g_woh[(size_t)DMODEL * DMODEL];
__device__ __half g_qh[(size_t)BB * NH * TT * DK];   // [b][h][t][d]
__device__ __half g_kh[(size_t)BB * NH * TT * DK];   // [b][h][t][d]
__device__ __half g_vh[(size_t)BB * NH * DK * TT];   // [b][h][d][t] (transposed)
__device__ __half g_attnh[(size_t)MROWS * DMODEL];   // attention out, fp16
__device__ float  g_cos[TT * 32];
__device__ float  g_sin[TT * 32];

// ---------------------------------------------------------------------------
__device__ __forceinline__ uint32_t pack_h2(float a, float b) {
    __half2 h = __floats2half2_rn(a, b);
    return *reinterpret_cast<uint32_t*>(&h);
}

// m16n8k16 f16, f32 accumulate.
// A: a0=(g,2t:2t+1) a1=(g+8,2t:+1) a2=(g,8+2t:+1) a3=(g+8,8+2t:+1)
// B (col-major view): b0=(k=2t:2t+1, n=g)  b1=(k=8+2t:+1, n=g)
// C: c0=(g,2t) c1=(g,2t+1) c2=(g+8,2t) c3=(g+8,2t+1)
__device__ __forceinline__ void mma_f16(float c[4],
                                        const uint32_t a[4],
                                        uint32_t b0, uint32_t b1) {
    asm volatile(
        "mma.sync.aligned.m16n8k16.row.col.f32.f16.f16.f32 "
        "{%0,%1,%2,%3}, {%4,%5,%6,%7}, {%8,%9}, {%0,%1,%2,%3};"
        : "+f"(c[0]), "+f"(c[1]), "+f"(c[2]), "+f"(c[3])
        : "r"(a[0]), "r"(a[1]), "r"(a[2]), "r"(a[3]), "r"(b0), "r"(b1));
}

__device__ __forceinline__ void ldsm_x4(uint32_t r[4], uint32_t addr) {
    asm volatile("ldmatrix.sync.aligned.m8n8.x4.shared.b16 {%0,%1,%2,%3}, [%4];"
        : "=r"(r[0]), "=r"(r[1]), "=r"(r[2]), "=r"(r[3]) : "r"(addr));
}

#define CP_ASYNC16(dst, src) \
    asm volatile("cp.async.ca.shared.global [%0], [%1], 16;" :: "r"(dst), "l"(src))
#define CP_COMMIT() asm volatile("cp.async.commit_group;")
#define CP_WAIT0()  asm volatile("cp.async.wait_group 0;")

// ---------------------------------------------------------------------------
// fp32 -> fp16 pre-pass for x and the four weight matrices.
// grid.y: 0=x (4M), 1..4 = Wq,Wk,Wv,Wo (1M each). 8 elems/thread.
// ---------------------------------------------------------------------------
__global__ void tohalf_kernel(const float* __restrict__ x,
                              const float* __restrict__ wq,
                              const float* __restrict__ wk,
                              const float* __restrict__ wv,
                              const float* __restrict__ wo) {
    const float* src; __half* dst; int n;
    switch (blockIdx.y) {
        case 0:  src = x;  dst = g_xh;  n = MROWS * DMODEL;   break;
        case 1:  src = wq; dst = g_wqh; n = DMODEL * DMODEL;  break;
        case 2:  src = wk; dst = g_wkh; n = DMODEL * DMODEL;  break;
        case 3:  src = wv; dst = g_wvh; n = DMODEL * DMODEL;  break;
        default: src = wo; dst = g_woh; n = DMODEL * DMODEL;  break;
    }
    int i = (blockIdx.x * blockDim.x + threadIdx.x) * 8;
    if (i >= n) return;
    float4 f0 = *(const float4*)(src + i);
    float4 f1 = *(const float4*)(src + i + 4);
    uint4 o = make_uint4(pack_h2(f0.x, f0.y), pack_h2(f0.z, f0.w),
                         pack_h2(f1.x, f1.y), pack_h2(f1.z, f1.w));
    *(uint4*)(dst + i) = o;
}

// ---------------------------------------------------------------------------
// RoPE tables + apply (fp16 q/k in place, fp32 math; Q pre-scaled).
// ---------------------------------------------------------------------------
__global__ void rope_table_kernel() {
    int i = blockIdx.x * blockDim.x + threadIdx.x;
    if (i >= TT * 32) return;
    int t = i >> 5, j = i & 31;
    double inv = pow(10000.0, -((double)(2 * j)) / 64.0);
    float angf = (float)t * (float)inv;
    g_cos[i] = (float)cos((double)angf);
    g_sin[i] = (float)sin((double)angf);
}

__global__ void rope_apply_kernel() {
    int i = blockIdx.x * blockDim.x + threadIdx.x;
    const int per = BB * NH * TT * 32;
    if (i >= 2 * per) return;
    const bool isq = (i < per);
    __half2* arr = (__half2*)(isq ? g_qh : g_kh);
    const float sc = isq ? (0.125f * 1.4426950408889634f) : 1.0f;
    int p = i & (per - 1);
    int j = p & 31;
    int bht = p >> 5;
    int t = bht & (TT - 1);
    float c = g_cos[t * 32 + j];
    float s = g_sin[t * 32 + j];
    size_t idx = (size_t)bht * 32 + j;
    float2 x = __half22float2(arr[idx]);
    arr[idx] = __floats2half2_rn((c * x.x - s * x.y) * sc,
                                 (s * x.x + c * x.y) * sc);
}

// ---------------------------------------------------------------------------
// FP16 GEMM: cp.async double-buffered + ldmatrix.x4 + m16n8k16.
// C[m,n] = sum_k A[m,k]*W[n,k] (NT), fp16 operands from __device__ globals
// (selected INSIDE the kernel — device symbols must not be host kernel args).
// Block 128x128, k-tile 64, 8 warps, warp tile 32(M)x64(N).
// MODE 0: A=g_xh, W={g_wqh,g_wkh,g_wvh}; scatter q/k -> g_qh/g_kh,
//         v -> g_vh transposed.
// MODE 1: A=g_attnh, W=g_woh, C=Cout fp32 (harness pointer).
// ---------------------------------------------------------------------------
#define LDH 72                    // smem leading dim in halfs (144B rows)
#define GBUF (128 * LDH)          // halfs per matrix buffer
#define GEMM_SMEM (4 * GBUF * 2)  // bytes: 2 stages x (A+B)
#define KTILES 16                 // 1024 / 64

template <int MODE>
__global__ void __launch_bounds__(256, 2) gemm_mma_kernel(float* __restrict__ Cout)
{
    extern __shared__ __half gsmh[];
    const uint32_t smem_u32 = (uint32_t)__cvta_generic_to_shared(gsmh);

    const int tid = threadIdx.x;
    const int warp = tid >> 5;
    const int lane = tid & 31;
    const int g = lane >> 2;
    const int t = lane & 3;
    const int wm = warp >> 1;               // 0..3 (M)
    const int wn = warp & 1;                // 0..1 (N)
    const int mb = blockIdx.x * 128;
    const int nb = blockIdx.y * 128;

    const __half* Ah = (MODE == 0) ? g_xh : g_attnh;
    const __half* Wp;
    int nloc;
    if (MODE == 0) {
        int w = nb >> 10;
        Wp = (w == 0) ? g_wqh : ((w == 1) ? g_wkh : g_wvh);
        nloc = nb & 1023;
    } else {
        Wp = g_woh;
        nloc = nb;
    }

    // ldmatrix per-thread byte offsets within a buffer
    const int arow = (lane & 7) + ((lane >> 3) & 1) * 8;
    const int akof = (lane >> 4) * 8;
    const int brow = (lane & 7) + ((lane >> 4) & 1) * 8;
    const int bkof = ((lane >> 3) & 1) * 8;
    uint32_t a_off[2], b_off[4];
#pragma unroll
    for (int i = 0; i < 2; i++)
        a_off[i] = ((wm * 32 + i * 16 + arow) * LDH + akof) * 2;
#pragma unroll
    for (int p = 0; p < 4; p++)
        b_off[p] = ((wn * 64 + p * 16 + brow) * LDH + bkof) * 2;

    float c[2][8][4];
#pragma unroll
    for (int i = 0; i < 2; i++)
#pragma unroll
        for (int nt = 0; nt < 8; nt++)
#pragma unroll
            for (int e = 0; e < 4; e++) c[i][nt][e] = 0.f;

    // ---- prologue: fill stage 0 ----
    {
        __half* As = gsmh;
        __half* Bs = gsmh + GBUF;
#pragma unroll
        for (int i = 0; i < 4; i++) {
            int cid = tid + 256 * i;
            int row = cid >> 3;
            int col = (cid & 7) * 8;
            uint32_t da = (uint32_t)__cvta_generic_to_shared(&As[row * LDH + col]);
            uint32_t db = (uint32_t)__cvta_generic_to_shared(&Bs[row * LDH + col]);
            CP_ASYNC16(da, Ah + (size_t)(mb + row) * 1024 + col);
            CP_ASYNC16(db, Wp + (size_t)(nloc + row) * 1024 + col);
        }
        CP_COMMIT();
    }

    for (int kt = 0; kt < KTILES; kt++) {
        CP_WAIT0();
        __syncthreads();

        if (kt + 1 < KTILES) {
            int kb = (kt + 1) * 64;
            __half* As = gsmh + ((kt + 1) & 1) * 2 * GBUF;
            __half* Bs = As + GBUF;
#pragma unroll
            for (int i = 0; i < 4; i++) {
                int cid = tid + 256 * i;
                int row = cid >> 3;
                int col = (cid & 7) * 8;
                uint32_t da = (uint32_t)__cvta_generic_to_shared(&As[row * LDH + col]);
                uint32_t db = (uint32_t)__cvta_generic_to_shared(&Bs[row * LDH + col]);
                CP_ASYNC16(da, Ah + (size_t)(mb + row) * 1024 + kb + col);
                CP_ASYNC16(db, Wp + (size_t)(nloc + row) * 1024 + kb + col);
            }
            CP_COMMIT();
        }

        const uint32_t abase = smem_u32 + (kt & 1) * 4 * GBUF;      // bytes
        const uint32_t bbase = abase + 2 * GBUF;

#pragma unroll
        for (int k0 = 0; k0 < 4; k0++) {        // 16-k steps within 64-k tile
            const uint32_t k0b = k0 * 32;       // 16 halfs = 32 bytes
            uint32_t af[2][4];
            ldsm_x4(af[0], abase + a_off[0] + k0b);
            ldsm_x4(af[1], abase + a_off[1] + k0b);
#pragma unroll
            for (int p = 0; p < 4; p++) {
                uint32_t bf[4];                 // b0(2p), b1(2p), b0(2p+1), b1(2p+1)
                ldsm_x4(bf, bbase + b_off[p] + k0b);
                mma_f16(c[0][2 * p],     af[0], bf[0], bf[1]);
                mma_f16(c[1][2 * p],     af[1], bf[0], bf[1]);
                mma_f16(c[0][2 * p + 1], af[0], bf[2], bf[3]);
                mma_f16(c[1][2 * p + 1], af[1], bf[2], bf[3]);
            }
        }
    }

    // ---- epilogue ----
#pragma unroll
    for (int i = 0; i < 2; i++) {
        int m0 = mb + wm * 32 + i * 16;
        int r0 = m0 + g, r1 = m0 + g + 8;
#pragma unroll
        for (int nt = 0; nt < 8; nt++) {
            int ncg = nb + wn * 64 + nt * 8 + 2 * t;
            float c0 = c[i][nt][0], c1 = c[i][nt][1];
            float c2 = c[i][nt][2], c3 = c[i][nt][3];
            if (MODE == 0) {
                int w = ncg >> 10;
                int hn = ncg & 1023;
                int hh = hn >> 6, dd = hn & 63;
                int bi0 = r0 >> 11, t0 = r0 & 2047;
                int bi1 = r1 >> 11, t1 = r1 & 2047;
                if (w < 2) {
                    __half* dst = (w == 0) ? g_qh : g_kh;
                    *(__half2*)&dst[((size_t)(bi0 * NH + hh) * TT + t0) * DK + dd] =
                        __floats2half2_rn(c0, c1);
                    *(__half2*)&dst[((size_t)(bi1 * NH + hh) * TT + t1) * DK + dd] =
                        __floats2half2_rn(c2, c3);
                } else {
                    // V transposed: [b][h][d][t]
                    size_t b0i = ((size_t)(bi0 * NH + hh) * DK + dd) * TT + t0;
                    g_vh[b0i]      = __float2half_rn(c0);
                    g_vh[b0i + TT] = __float2half_rn(c1);
                    size_t b1i = ((size_t)(bi1 * NH + hh) * DK + dd) * TT + t1;
                    g_vh[b1i]      = __float2half_rn(c2);
                    g_vh[b1i + TT] = __float2half_rn(c3);
                }
            } else {
                *(float2*)&Cout[(size_t)r0 * DMODEL + ncg] = make_float2(c0, c1);
                *(float2*)&Cout[(size_t)r1 * DMODEL + ncg] = make_float2(c2, c3);
            }
        }
    }
}

// ---------------------------------------------------------------------------
// Flash attention, fp16 m16n8k16 (R10-passing structure; output fp16 into
// g_attnh for the out-projection GEMM).
// smem: Ks[64][72] halfs ([c][d]), Vt[64][72] halfs ([d][c]).
// ---------------------------------------------------------------------------
#define LDKH 72
#define FLASH_SMEM (2 * 64 * LDKH * 2)

__global__ void __launch_bounds__(256, 2) flash_mma_kernel() {
    extern __shared__ __half fsh[];
    __half* Ks = fsh;                   // [c][d]
    __half* Vt = fsh + 64 * LDKH;       // [d][c]

    const int qt = blockIdx.x;
    const int h  = blockIdx.y;
    const int bz = blockIdx.z;
    const int tid = threadIdx.x;
    const int lane = tid & 31;
    const int w = tid >> 5;
    const int g = lane >> 2;
    const int t = lane & 3;

    const size_t head_off = (size_t)(bz * NH + h) * TT * DK;
    const int rbase = qt * 128 + w * 16;

    const __half* kbase = g_kh + head_off;
    const __half* vbase = g_vh + (size_t)(bz * NH + h) * DK * TT;

    // ---- Q fragments (fp16, pre-scaled by rope) ----
    uint32_t qf[4][4];
    {
        const __half* qp = g_qh + head_off + (size_t)rbase * DK;
#pragma unroll
        for (int kc = 0; kc < 4; kc++) {
            qf[kc][0] = *(const uint32_t*)&qp[(size_t)g * DK + 16 * kc + 2 * t];
            qf[kc][1] = *(const uint32_t*)&qp[(size_t)(g + 8) * DK + 16 * kc + 2 * t];
            qf[kc][2] = *(const uint32_t*)&qp[(size_t)g * DK + 16 * kc + 8 + 2 * t];
            qf[kc][3] = *(const uint32_t*)&qp[(size_t)(g + 8) * DK + 16 * kc + 8 + 2 * t];
        }
    }

    float oa[8][4];
#pragma unroll
    for (int i = 0; i < 8; i++)
#pragma unroll
        for (int j = 0; j < 4; j++) oa[i][j] = 0.f;
    float m0 = -1e30f, m1 = -1e30f, l0 = 0.f, l1 = 0.f;

    const int ktiles = 2 * qt + 2;
    for (int j = 0; j < ktiles; j++) {
        __syncthreads();
        {
            const __half* kp = kbase + (size_t)j * 64 * DK;
            const __half* vp = vbase + 64 * j;
#pragma unroll
            for (int i = 0; i < 2; i++) {
                int f8 = tid + 256 * i;          // 8-half (16B) chunk id
                int r = f8 >> 3, cq = (f8 & 7) * 8;
                *(uint4*)&Ks[r * LDKH + cq] = *(const uint4*)(kp + r * DK + cq);
                *(uint4*)&Vt[r * LDKH + cq] = *(const uint4*)(vp + (size_t)r * TT + cq);
            }
        }
        __syncthreads();

        if (64 * j > rbase + 15) continue;

        const uint32_t* Ks_u = (const uint32_t*)Ks;
        const uint32_t* Vt_u = (const uint32_t*)Vt;

        // ---- S = Q K^T ----
        float sa[8][4];
#pragma unroll
        for (int nt = 0; nt < 8; nt++) {
            sa[nt][0] = sa[nt][1] = sa[nt][2] = sa[nt][3] = 0.f;
#pragma unroll
            for (int kc = 0; kc < 4; kc++) {
                uint32_t b0 = Ks_u[(8 * nt + g) * (LDKH / 2) + 8 * kc + t];
                uint32_t b1 = Ks_u[(8 * nt + g) * (LDKH / 2) + 8 * kc + 4 + t];
                mma_f16(sa[nt], qf[kc], b0, b1);
            }
        }

        // ---- causal mask (diagonal region only) ----
        if (64 * j + 63 > rbase) {
            const int r0 = rbase + g, r1 = rbase + g + 8;
#pragma unroll
            for (int nt = 0; nt < 8; nt++) {
                int c0 = 64 * j + 8 * nt + 2 * t;
                if (c0 > r0)     sa[nt][0] = -1e30f;
                if (c0 + 1 > r0) sa[nt][1] = -1e30f;
                if (c0 > r1)     sa[nt][2] = -1e30f;
                if (c0 + 1 > r1) sa[nt][3] = -1e30f;
            }
        }

        // ---- online softmax (registers + quad shuffles) ----
        float mx0 = -1e30f, mx1 = -1e30f;
#pragma unroll
        for (int nt = 0; nt < 8; nt++) {
            mx0 = fmaxf(mx0, fmaxf(sa[nt][0], sa[nt][1]));
            mx1 = fmaxf(mx1, fmaxf(sa[nt][2], sa[nt][3]));
        }
        mx0 = fmaxf(mx0, __shfl_xor_sync(0xffffffffu, mx0, 1));
        mx0 = fmaxf(mx0, __shfl_xor_sync(0xffffffffu, mx0, 2));
        mx1 = fmaxf(mx1, __shfl_xor_sync(0xffffffffu, mx1, 1));
        mx1 = fmaxf(mx1, __shfl_xor_sync(0xffffffffu, mx1, 2));
        float mn0 = fmaxf(m0, mx0), mn1 = fmaxf(m1, mx1);
        float al0 = exp2f(m0 - mn0), al1 = exp2f(m1 - mn1);
        m0 = mn0; m1 = mn1;

        float sum0 = 0.f, sum1 = 0.f;
#pragma unroll
        for (int nt = 0; nt < 8; nt++) {
            float p0 = exp2f(sa[nt][0] - mn0);
            float p1 = exp2f(sa[nt][1] - mn0);
            float p2 = exp2f(sa[nt][2] - mn1);
            float p3 = exp2f(sa[nt][3] - mn1);
            sum0 += p0 + p1;
            sum1 += p2 + p3;
            sa[nt][0] = p0; sa[nt][1] = p1; sa[nt][2] = p2; sa[nt][3] = p3;
        }
        sum0 += __shfl_xor_sync(0xffffffffu, sum0, 1);
        sum0 += __shfl_xor_sync(0xffffffffu, sum0, 2);
        sum1 += __shfl_xor_sync(0xffffffffu, sum1, 1);
        sum1 += __shfl_xor_sync(0xffffffffu, sum1, 2);
        l0 = l0 * al0 + sum0;
        l1 = l1 * al1 + sum1;

#pragma unroll
        for (int dt = 0; dt < 8; dt++) {
            oa[dt][0] *= al0; oa[dt][1] *= al0;
            oa[dt][2] *= al1; oa[dt][3] *= al1;
        }

        // ---- pack P to fp16 A-fragments (registers only) ----
        uint32_t pf[4][4];
#pragma unroll
        for (int kc = 0; kc < 4; kc++) {
            pf[kc][0] = pack_h2(sa[2 * kc][0],     sa[2 * kc][1]);
            pf[kc][1] = pack_h2(sa[2 * kc][2],     sa[2 * kc][3]);
            pf[kc][2] = pack_h2(sa[2 * kc + 1][0], sa[2 * kc + 1][1]);
            pf[kc][3] = pack_h2(sa[2 * kc + 1][2], sa[2 * kc + 1][3]);
        }

        // ---- O += P V ----
#pragma unroll
        for (int kc = 0; kc < 4; kc++) {
#pragma unroll
            for (int dt = 0; dt < 8; dt++) {
                uint32_t b0 = Vt_u[(8 * dt + g) * (LDKH / 2) + 8 * kc + t];
                uint32_t b1 = Vt_u[(8 * dt + g) * (LDKH / 2) + 8 * kc + 4 + t];
                mma_f16(oa[dt], pf[kc], b0, b1);
            }
        }
    }

    // ---- normalize & write fp16 [b*t][e] ----
    {
        float inv0 = 1.f / l0, inv1 = 1.f / l1;
        __half* op0 = g_attnh + (size_t)(bz * TT + rbase + g) * DMODEL + h * DK;
        __half* op1 = g_attnh + (size_t)(bz * TT + rbase + g + 8) * DMODEL + h * DK;
#pragma unroll
        for (int dt = 0; dt < 8; dt++) {
            *(uint32_t*)&op0[8 * dt + 2 * t] = pack_h2(oa[dt][0] * inv0, oa[dt][1] * inv0);
            *(uint32_t*)&op1[8 * dt + 2 * t] = pack_h2(oa[dt][2] * inv1, oa[dt][3] * inv1);
        }
    }
}

// ---------------------------------------------------------------------------
extern "C" void kernel_launch(void* const* d_in, const int* in_sizes, int n_in,
                              void* d_out, int out_size) {
    (void)in_sizes; (void)n_in; (void)out_size;
    const float* x  = (const float*)d_in[0];
    const float* Wq = (const float*)d_in[2];
    const float* Wk = (const float*)d_in[3];
    const float* Wv = (const float*)d_in[4];
    const float* Wo = (const float*)d_in[5];
    float* out = (float*)d_out;

    cudaFuncSetAttribute(flash_mma_kernel,
                         cudaFuncAttributeMaxDynamicSharedMemorySize, FLASH_SMEM);
    cudaFuncSetAttribute(gemm_mma_kernel<0>,
                         cudaFuncAttributeMaxDynamicSharedMemorySize, GEMM_SMEM);
    cudaFuncSetAttribute(gemm_mma_kernel<1>,
                         cudaFuncAttributeMaxDynamicSharedMemorySize, GEMM_SMEM);

    tohalf_kernel<<<dim3(2048, 5), 256>>>(x, Wq, Wk, Wv, Wo);

    rope_table_kernel<<<(TT * 32 + 255) / 256, 256>>>();

    gemm_mma_kernel<0><<<dim3(MROWS / 128, 3072 / 128), 256, GEMM_SMEM>>>(nullptr);

    rope_apply_kernel<<<(2 * BB * NH * TT * 32 + 255) / 256, 256>>>();

    flash_mma_kernel<<<dim3(TT / 128, NH, BB), 256, FLASH_SMEM>>>();

    gemm_mma_kernel<1><<<dim3(MROWS / 128, DMODEL / 128), 256, GEMM_SMEM>>>(out);
}

// round 13
// speedup vs baseline: 1.2850x; 1.2850x over previous
#include <cuda_runtime.h>
#include <cuda_fp16.h>
#include <math.h>
#include <stdint.h>

#define BB 2
#define TT 2048
#define DMODEL 1024
#define NH 16
#define DK 64
#define MROWS (BB * TT)   // 4096

// ---- scratch (static device memory; no allocations allowed) ----
__device__ __half g_qh[(size_t)BB * NH * TT * DK];   // [b][h][t][d] roped+scaled
__device__ __half g_kh[(size_t)BB * NH * TT * DK];   // [b][h][t][d] roped
__device__ __half g_vh[(size_t)BB * NH * DK * TT];   // [b][h][d][t] (transposed)
__device__ __half g_attnh[(size_t)MROWS * DMODEL];   // attention out, fp16
__device__ float  g_cos[TT * 32];
__device__ float  g_sin[TT * 32];

// ---------------------------------------------------------------------------
__device__ __forceinline__ uint32_t pack_h2(float a, float b) {
    __half2 h = __floats2half2_rn(a, b);
    return *reinterpret_cast<uint32_t*>(&h);
}

// m16n8k16 f16, f32 accumulate.
// A: a0=(g,2t:2t+1) a1=(g+8,2t:+1) a2=(g,8+2t:+1) a3=(g+8,8+2t:+1)
// B (col-major view): b0=(k=2t:2t+1, n=g)  b1=(k=8+2t:+1, n=g)
// C: c0=(g,2t) c1=(g,2t+1) c2=(g+8,2t) c3=(g+8,2t+1)
__device__ __forceinline__ void mma_f16(float c[4],
                                        const uint32_t a[4],
                                        uint32_t b0, uint32_t b1) {
    asm volatile(
        "mma.sync.aligned.m16n8k16.row.col.f32.f16.f16.f32 "
        "{%0,%1,%2,%3}, {%4,%5,%6,%7}, {%8,%9}, {%0,%1,%2,%3};"
        : "+f"(c[0]), "+f"(c[1]), "+f"(c[2]), "+f"(c[3])
        : "r"(a[0]), "r"(a[1]), "r"(a[2]), "r"(a[3]), "r"(b0), "r"(b1));
}

// ---------------------------------------------------------------------------
// RoPE tables (applied inside the QKV-GEMM epilogue).
// ---------------------------------------------------------------------------
__global__ void rope_table_kernel() {
    int i = blockIdx.x * blockDim.x + threadIdx.x;
    if (i >= TT * 32) return;
    int t = i >> 5, j = i & 31;
    double inv = pow(10000.0, -((double)(2 * j)) / 64.0);
    float angf = (float)t * (float)inv;
    g_cos[i] = (float)cos((double)angf);
    g_sin[i] = (float)sin((double)angf);
}

// ---------------------------------------------------------------------------
// FP16 raw-mma GEMM (R10-proven structure: register staging + double smem
// buffer, fp16 smem tiles converted at fill, scalar-LDS fragment loads).
// C[m,n] = sum_k A[m,k]*W[n,k] (NT). Block 128x128, k-tile 32, 8 warps,
// warp tile 32(M)x64(N) = 2 m-frags x 8 n-frags of m16n8k16.
// MODE 0: A=x (fp32), W={Wq,Wk,Wv} (fp32); epilogue applies RoPE (+Q scale)
//         and scatters q/k -> g_qh/g_kh [b][h][t][d], v -> g_vh transposed.
// MODE 1: A=g_attnh (fp16, internal symbol), W=Wo (fp32), C=out fp32.
// ---------------------------------------------------------------------------
#define LDH 40                    // smem leading dim in halfs
#define GBUF_H (128 * LDH)        // halfs per A (or B) buffer
#define GEMM_SMEM (4 * GBUF_H * 2)

template <int MODE>
__global__ void __launch_bounds__(256, 2) gemm_mma_kernel(
    const float* __restrict__ A_,
    const float* __restrict__ W0,
    const float* __restrict__ W1,
    const float* __restrict__ W2,
    float* __restrict__ Cout)
{
    extern __shared__ __half gsmh[];

    const int tid = threadIdx.x;
    const int warp = tid >> 5;
    const int lane = tid & 31;
    const int g = lane >> 2;
    const int t = lane & 3;
    const int wm = warp >> 1;
    const int wn = warp & 1;
    const int mb = blockIdx.x * 128;
    const int nb = blockIdx.y * 128;

    const float* Wp;
    int nloc;
    if (MODE == 0) {
        int w = nb >> 10;
        Wp = (w == 0) ? W0 : ((w == 1) ? W1 : W2);
        nloc = nb & 1023;
    } else {
        Wp = W0;
        nloc = nb;
    }

    const int lrow = tid >> 3;          // base row, step 32
    const int lkq  = (tid & 7) << 2;    // k offset (4 elements)

    float4 stB[4];
    float4 stA[4];                      // MODE 0 (fp32 A)
    uint2  stAh[4];                     // MODE 1 (fp16 A)

#pragma unroll
    for (int i = 0; i < 4; i++) {
        int row = lrow + 32 * i;
        if (MODE == 0)
            stA[i] = *(const float4*)(A_ + (size_t)(mb + row) * 1024 + lkq);
        else
            stAh[i] = *(const uint2*)(g_attnh + (size_t)(mb + row) * 1024 + lkq);
        stB[i] = *(const float4*)(Wp + (size_t)(nloc + row) * 1024 + lkq);
    }
    {
        __half* As = gsmh;
        __half* Bs = gsmh + GBUF_H;
#pragma unroll
        for (int i = 0; i < 4; i++) {
            int row = lrow + 32 * i;
            if (MODE == 0)
                *(uint2*)&As[row * LDH + lkq] =
                    make_uint2(pack_h2(stA[i].x, stA[i].y), pack_h2(stA[i].z, stA[i].w));
            else
                *(uint2*)&As[row * LDH + lkq] = stAh[i];
            *(uint2*)&Bs[row * LDH + lkq] =
                make_uint2(pack_h2(stB[i].x, stB[i].y), pack_h2(stB[i].z, stB[i].w));
        }
    }
    __syncthreads();

    float c[2][8][4];
#pragma unroll
    for (int i = 0; i < 2; i++)
#pragma unroll
        for (int nt = 0; nt < 8; nt++)
#pragma unroll
            for (int e = 0; e < 4; e++) c[i][nt][e] = 0.f;

    for (int kt = 0; kt < 32; kt++) {
        if (kt + 1 < 32) {
            int kb = (kt + 1) * 32;
#pragma unroll
            for (int i = 0; i < 4; i++) {
                int row = lrow + 32 * i;
                if (MODE == 0)
                    stA[i] = *(const float4*)(A_ + (size_t)(mb + row) * 1024 + kb + lkq);
                else
                    stAh[i] = *(const uint2*)(g_attnh + (size_t)(mb + row) * 1024 + kb + lkq);
                stB[i] = *(const float4*)(Wp + (size_t)(nloc + row) * 1024 + kb + lkq);
            }
        }

        const uint32_t* As_u = (const uint32_t*)(gsmh + (kt & 1) * 2 * GBUF_H);
        const uint32_t* Bs_u = As_u + GBUF_H / 2;

#pragma unroll
        for (int k0 = 0; k0 < 2; k0++) {            // k0h = 0, 8 (uint units)
            const int k0h = k0 * 8;
            uint32_t af[2][4];
#pragma unroll
            for (int i = 0; i < 2; i++) {
                int m0 = wm * 32 + i * 16;
                af[i][0] = As_u[(m0 + g)     * (LDH / 2) + k0h + t];
                af[i][1] = As_u[(m0 + g + 8) * (LDH / 2) + k0h + t];
                af[i][2] = As_u[(m0 + g)     * (LDH / 2) + k0h + 4 + t];
                af[i][3] = As_u[(m0 + g + 8) * (LDH / 2) + k0h + 4 + t];
            }
#pragma unroll
            for (int nt = 0; nt < 8; nt++) {
                int n0 = wn * 64 + nt * 8;
                uint32_t b0 = Bs_u[(n0 + g) * (LDH / 2) + k0h + t];
                uint32_t b1 = Bs_u[(n0 + g) * (LDH / 2) + k0h + 4 + t];
                mma_f16(c[0][nt], af[0], b0, b1);
                mma_f16(c[1][nt], af[1], b0, b1);
            }
        }

        if (kt + 1 < 32) {
            __half* Asn = gsmh + ((kt + 1) & 1) * 2 * GBUF_H;
            __half* Bsn = Asn + GBUF_H;
#pragma unroll
            for (int i = 0; i < 4; i++) {
                int row = lrow + 32 * i;
                if (MODE == 0)
                    *(uint2*)&Asn[row * LDH + lkq] =
                        make_uint2(pack_h2(stA[i].x, stA[i].y), pack_h2(stA[i].z, stA[i].w));
                else
                    *(uint2*)&Asn[row * LDH + lkq] = stAh[i];
                *(uint2*)&Bsn[row * LDH + lkq] =
                    make_uint2(pack_h2(stB[i].x, stB[i].y), pack_h2(stB[i].z, stB[i].w));
            }
            __syncthreads();
        }
    }

    // ---- epilogue (MODE 0: fused RoPE on q/k; V transposed) ----
    const float SCALE = 0.125f * 1.4426950408889634f;
#pragma unroll
    for (int i = 0; i < 2; i++) {
        int m0 = mb + wm * 32 + i * 16;
        int r0 = m0 + g, r1 = m0 + g + 8;
#pragma unroll
        for (int nt = 0; nt < 8; nt++) {
            int ncg = nb + wn * 64 + nt * 8 + 2 * t;
            float c0 = c[i][nt][0], c1 = c[i][nt][1];
            float c2 = c[i][nt][2], c3 = c[i][nt][3];
            if (MODE == 0) {
                int w = ncg >> 10;
                int hn = ncg & 1023;
                int hh = hn >> 6, dd = hn & 63;        // dd even
                int bi0 = r0 >> 11, t0 = r0 & 2047;
                int bi1 = r1 >> 11, t1 = r1 & 2047;
                if (w < 2) {
                    // rope pair (j = dd/2) on (c0,c1) and (c2,c3)
                    int j = dd >> 1;
                    float cs0 = g_cos[t0 * 32 + j], sn0 = g_sin[t0 * 32 + j];
                    float cs1 = g_cos[t1 * 32 + j], sn1 = g_sin[t1 * 32 + j];
                    float o00 = cs0 * c0 - sn0 * c1;
                    float o01 = sn0 * c0 + cs0 * c1;
                    float o10 = cs1 * c2 - sn1 * c3;
                    float o11 = sn1 * c2 + cs1 * c3;
                    if (w == 0) { o00 *= SCALE; o01 *= SCALE; o10 *= SCALE; o11 *= SCALE; }
                    __half* dst = (w == 0) ? g_qh : g_kh;
                    *(__half2*)&dst[((size_t)(bi0 * NH + hh) * TT + t0) * DK + dd] =
                        __floats2half2_rn(o00, o01);
                    *(__half2*)&dst[((size_t)(bi1 * NH + hh) * TT + t1) * DK + dd] =
                        __floats2half2_rn(o10, o11);
                } else {
                    // V transposed: [b][h][d][t]
                    size_t b0i = ((size_t)(bi0 * NH + hh) * DK + dd) * TT + t0;
                    g_vh[b0i]      = __float2half_rn(c0);
                    g_vh[b0i + TT] = __float2half_rn(c1);
                    size_t b1i = ((size_t)(bi1 * NH + hh) * DK + dd) * TT + t1;
                    g_vh[b1i]      = __float2half_rn(c2);
                    g_vh[b1i + TT] = __float2half_rn(c3);
                }
            } else {
                *(float2*)&Cout[(size_t)r0 * DMODEL + ncg] = make_float2(c0, c1);
                *(float2*)&Cout[(size_t)r1 * DMODEL + ncg] = make_float2(c2, c3);
            }
        }
    }
}

// ---------------------------------------------------------------------------
// Flash attention, fp16 m16n8k16 (R10-proven structure). qt DESCENDING for
// wave balance; output fp16 into g_attnh.
// smem: Ks[64][72] halfs ([c][d]), Vt[64][72] halfs ([d][c]).
// ---------------------------------------------------------------------------
#define LDKH 72
#define FLASH_SMEM (2 * 64 * LDKH * 2)

__global__ void __launch_bounds__(256, 2) flash_mma_kernel() {
    extern __shared__ __half fsh[];
    __half* Ks = fsh;                   // [c][d]
    __half* Vt = fsh + 64 * LDKH;       // [d][c]

    const int qt = (gridDim.x - 1) - blockIdx.x;   // long CTAs first
    const int h  = blockIdx.y;
    const int bz = blockIdx.z;
    const int tid = threadIdx.x;
    const int lane = tid & 31;
    const int w = tid >> 5;
    const int g = lane >> 2;
    const int t = lane & 3;

    const size_t head_off = (size_t)(bz * NH + h) * TT * DK;
    const int rbase = qt * 128 + w * 16;

    const __half* kbase = g_kh + head_off;
    const __half* vbase = g_vh + (size_t)(bz * NH + h) * DK * TT;

    // ---- Q fragments (fp16, roped + pre-scaled by GEMM epilogue) ----
    uint32_t qf[4][4];
    {
        const __half* qp = g_qh + head_off + (size_t)rbase * DK;
#pragma unroll
        for (int kc = 0; kc < 4; kc++) {
            qf[kc][0] = *(const uint32_t*)&qp[(size_t)g * DK + 16 * kc + 2 * t];
            qf[kc][1] = *(const uint32_t*)&qp[(size_t)(g + 8) * DK + 16 * kc + 2 * t];
            qf[kc][2] = *(const uint32_t*)&qp[(size_t)g * DK + 16 * kc + 8 + 2 * t];
            qf[kc][3] = *(const uint32_t*)&qp[(size_t)(g + 8) * DK + 16 * kc + 8 + 2 * t];
        }
    }

    float oa[8][4];
#pragma unroll
    for (int i = 0; i < 8; i++)
#pragma unroll
        for (int j = 0; j < 4; j++) oa[i][j] = 0.f;
    float m0 = -1e30f, m1 = -1e30f, l0 = 0.f, l1 = 0.f;

    const int ktiles = 2 * qt + 2;
    for (int j = 0; j < ktiles; j++) {
        __syncthreads();
        {
            const __half* kp = kbase + (size_t)j * 64 * DK;
            const __half* vp = vbase + 64 * j;
#pragma unroll
            for (int i = 0; i < 2; i++) {
                int f8 = tid + 256 * i;          // 8-half (16B) chunk id
                int r = f8 >> 3, cq = (f8 & 7) * 8;
                *(uint4*)&Ks[r * LDKH + cq] = *(const uint4*)(kp + r * DK + cq);
                *(uint4*)&Vt[r * LDKH + cq] = *(const uint4*)(vp + (size_t)r * TT + cq);
            }
        }
        __syncthreads();

        if (64 * j > rbase + 15) continue;

        const uint32_t* Ks_u = (const uint32_t*)Ks;
        const uint32_t* Vt_u = (const uint32_t*)Vt;

        // ---- S = Q K^T ----
        float sa[8][4];
#pragma unroll
        for (int nt = 0; nt < 8; nt++) {
            sa[nt][0] = sa[nt][1] = sa[nt][2] = sa[nt][3] = 0.f;
#pragma unroll
            for (int kc = 0; kc < 4; kc++) {
                uint32_t b0 = Ks_u[(8 * nt + g) * (LDKH / 2) + 8 * kc + t];
                uint32_t b1 = Ks_u[(8 * nt + g) * (LDKH / 2) + 8 * kc + 4 + t];
                mma_f16(sa[nt], qf[kc], b0, b1);
            }
        }

        // ---- causal mask (diagonal region only) ----
        if (64 * j + 63 > rbase) {
            const int r0 = rbase + g, r1 = rbase + g + 8;
#pragma unroll
            for (int nt = 0; nt < 8; nt++) {
                int c0 = 64 * j + 8 * nt + 2 * t;
                if (c0 > r0)     sa[nt][0] = -1e30f;
                if (c0 + 1 > r0) sa[nt][1] = -1e30f;
                if (c0 > r1)     sa[nt][2] = -1e30f;
                if (c0 + 1 > r1) sa[nt][3] = -1e30f;
            }
        }

        // ---- online softmax (registers + quad shuffles) ----
        float mx0 = -1e30f, mx1 = -1e30f;
#pragma unroll
        for (int nt = 0; nt < 8; nt++) {
            mx0 = fmaxf(mx0, fmaxf(sa[nt][0], sa[nt][1]));
            mx1 = fmaxf(mx1, fmaxf(sa[nt][2], sa[nt][3]));
        }
        mx0 = fmaxf(mx0, __shfl_xor_sync(0xffffffffu, mx0, 1));
        mx0 = fmaxf(mx0, __shfl_xor_sync(0xffffffffu, mx0, 2));
        mx1 = fmaxf(mx1, __shfl_xor_sync(0xffffffffu, mx1, 1));
        mx1 = fmaxf(mx1, __shfl_xor_sync(0xffffffffu, mx1, 2));
        float mn0 = fmaxf(m0, mx0), mn1 = fmaxf(m1, mx1);
        float al0 = exp2f(m0 - mn0), al1 = exp2f(m1 - mn1);
        m0 = mn0; m1 = mn1;

        float sum0 = 0.f, sum1 = 0.f;
#pragma unroll
        for (int nt = 0; nt < 8; nt++) {
            float p0 = exp2f(sa[nt][0] - mn0);
            float p1 = exp2f(sa[nt][1] - mn0);
            float p2 = exp2f(sa[nt][2] - mn1);
            float p3 = exp2f(sa[nt][3] - mn1);
            sum0 += p0 + p1;
            sum1 += p2 + p3;
            sa[nt][0] = p0; sa[nt][1] = p1; sa[nt][2] = p2; sa[nt][3] = p3;
        }
        sum0 += __shfl_xor_sync(0xffffffffu, sum0, 1);
        sum0 += __shfl_xor_sync(0xffffffffu, sum0, 2);
        sum1 += __shfl_xor_sync(0xffffffffu, sum1, 1);
        sum1 += __shfl_xor_sync(0xffffffffu, sum1, 2);
        l0 = l0 * al0 + sum0;
        l1 = l1 * al1 + sum1;

#pragma unroll
        for (int dt = 0; dt < 8; dt++) {
            oa[dt][0] *= al0; oa[dt][1] *= al0;
            oa[dt][2] *= al1; oa[dt][3] *= al1;
        }

        // ---- pack P to fp16 A-fragments (registers only) ----
        uint32_t pf[4][4];
#pragma unroll
        for (int kc = 0; kc < 4; kc++) {
            pf[kc][0] = pack_h2(sa[2 * kc][0],     sa[2 * kc][1]);
            pf[kc][1] = pack_h2(sa[2 * kc][2],     sa[2 * kc][3]);
            pf[kc][2] = pack_h2(sa[2 * kc + 1][0], sa[2 * kc + 1][1]);
            pf[kc][3] = pack_h2(sa[2 * kc + 1][2], sa[2 * kc + 1][3]);
        }

        // ---- O += P V ----
#pragma unroll
        for (int kc = 0; kc < 4; kc++) {
#pragma unroll
            for (int dt = 0; dt < 8; dt++) {
                uint32_t b0 = Vt_u[(8 * dt + g) * (LDKH / 2) + 8 * kc + t];
                uint32_t b1 = Vt_u[(8 * dt + g) * (LDKH / 2) + 8 * kc + 4 + t];
                mma_f16(oa[dt], pf[kc], b0, b1);
            }
        }
    }

    // ---- normalize & write fp16 [b*t][e] ----
    {
        float inv0 = 1.f / l0, inv1 = 1.f / l1;
        __half* op0 = g_attnh + (size_t)(bz * TT + rbase + g) * DMODEL + h * DK;
        __half* op1 = g_attnh + (size_t)(bz * TT + rbase + g + 8) * DMODEL + h * DK;
#pragma unroll
        for (int dt = 0; dt < 8; dt++) {
            *(uint32_t*)&op0[8 * dt + 2 * t] = pack_h2(oa[dt][0] * inv0, oa[dt][1] * inv0);
            *(uint32_t*)&op1[8 * dt + 2 * t] = pack_h2(oa[dt][2] * inv1, oa[dt][3] * inv1);
        }
    }
}

// ---------------------------------------------------------------------------
extern "C" void kernel_launch(void* const* d_in, const int* in_sizes, int n_in,
                              void* d_out, int out_size) {
    (void)in_sizes; (void)n_in; (void)out_size;
    const float* x  = (const float*)d_in[0];
    const float* Wq = (const float*)d_in[2];
    const float* Wk = (const float*)d_in[3];
    const float* Wv = (const float*)d_in[4];
    const float* Wo = (const float*)d_in[5];
    float* out = (float*)d_out;

    cudaFuncSetAttribute(flash_mma_kernel,
                         cudaFuncAttributeMaxDynamicSharedMemorySize, FLASH_SMEM);
    cudaFuncSetAttribute(gemm_mma_kernel<0>,
                         cudaFuncAttributeMaxDynamicSharedMemorySize, GEMM_SMEM);
    cudaFuncSetAttribute(gemm_mma_kernel<1>,
                         cudaFuncAttributeMaxDynamicSharedMemorySize, GEMM_SMEM);

    rope_table_kernel<<<(TT * 32 + 255) / 256, 256>>>();

    gemm_mma_kernel<0><<<dim3(MROWS / 128, 3072 / 128), 256, GEMM_SMEM>>>(
        x, Wq, Wk, Wv, nullptr);

    flash_mma_kernel<<<dim3(TT / 128, NH, BB), 256, FLASH_SMEM>>>();

    gemm_mma_kernel<1><<<dim3(MROWS / 128, DMODEL / 128), 256, GEMM_SMEM>>>(
        nullptr, Wo, nullptr, nullptr, out);
}

// round 15
// speedup vs baseline: 1.3741x; 1.0693x over previous
#include <cuda_runtime.h>
#include <cuda_fp16.h>
#include <math.h>
#include <stdint.h>

#define BB 2
#define TT 2048
#define DMODEL 1024
#define NH 16
#define DK 64
#define MROWS (BB * TT)   // 4096

// ---- scratch (static device memory; no allocations allowed) ----
__device__ __half g_qh[(size_t)BB * NH * TT * DK];   // [b][h][t][d] roped+scaled
__device__ __half g_kh[(size_t)BB * NH * TT * DK];   // [b][h][t][d] roped
__device__ __half g_vh[(size_t)BB * NH * DK * TT];   // [b][h][d][t] (transposed)
__device__ __half g_attnh[(size_t)MROWS * DMODEL];   // attention out, fp16
__device__ float  g_cos[TT * 32];
__device__ float  g_sin[TT * 32];

// ---------------------------------------------------------------------------
__device__ __forceinline__ uint32_t pack_h2(float a, float b) {
    __half2 h = __floats2half2_rn(a, b);
    return *reinterpret_cast<uint32_t*>(&h);
}

// m16n8k16 f16, f32 accumulate.
// A: a0=(g,2t:2t+1) a1=(g+8,2t:+1) a2=(g,8+2t:+1) a3=(g+8,8+2t:+1)
// B (col-major view): b0=(k=2t:2t+1, n=g)  b1=(k=8+2t:+1, n=g)
// C: c0=(g,2t) c1=(g,2t+1) c2=(g+8,2t) c3=(g+8,2t+1)
__device__ __forceinline__ void mma_f16(float c[4],
                                        const uint32_t a[4],
                                        uint32_t b0, uint32_t b1) {
    asm volatile(
        "mma.sync.aligned.m16n8k16.row.col.f32.f16.f16.f32 "
        "{%0,%1,%2,%3}, {%4,%5,%6,%7}, {%8,%9}, {%0,%1,%2,%3};"
        : "+f"(c[0]), "+f"(c[1]), "+f"(c[2]), "+f"(c[3])
        : "r"(a[0]), "r"(a[1]), "r"(a[2]), "r"(a[3]), "r"(b0), "r"(b1));
}

// ---------------------------------------------------------------------------
// RoPE tables (applied inside the QKV-GEMM epilogue).
// ---------------------------------------------------------------------------
__global__ void rope_table_kernel() {
    int i = blockIdx.x * blockDim.x + threadIdx.x;
    if (i >= TT * 32) return;
    int t = i >> 5, j = i & 31;
    double inv = pow(10000.0, -((double)(2 * j)) / 64.0);
    float angf = (float)t * (float)inv;
    g_cos[i] = (float)cos((double)angf);
    g_sin[i] = (float)sin((double)angf);
}

// ---------------------------------------------------------------------------
// FP16 raw-mma GEMM, warp tile 64Mx64N, CTA 256Mx128N, k-tile 32, occ 1.
// Register staging + double smem buffer; fp16 smem tiles converted at fill.
// C[m,n] = sum_k A[m,k]*W[n,k] (NT).
// MODE 0: A=x (fp32), W={Wq,Wk,Wv} (fp32); epilogue applies RoPE (+Q scale),
//         scatters q/k -> g_qh/g_kh [b][h][t][d], v -> g_vh transposed.
// MODE 1: A=g_attnh (fp16, internal symbol), W=Wo (fp32), C=out fp32.
// ---------------------------------------------------------------------------
#define LDH 40                        // smem leading dim in halfs
#define ABUF_H (256 * LDH)            // halfs per A buffer
#define BBUF_H (128 * LDH)            // halfs per B buffer
#define STAGE_H (ABUF_H + BBUF_H)
#define GEMM_SMEM (2 * STAGE_H * 2)   // bytes

template <int MODE>
__global__ void __launch_bounds__(256, 1) gemm_mma_kernel(
    const float* __restrict__ A_,
    const float* __restrict__ W0,
    const float* __restrict__ W1,
    const float* __restrict__ W2,
    float* __restrict__ Cout)
{
    extern __shared__ __half gsmh[];

    const int tid = threadIdx.x;
    const int warp = tid >> 5;
    const int lane = tid & 31;
    const int g = lane >> 2;
    const int t = lane & 3;
    const int wm = warp >> 1;            // 0..3 (M, 64 rows each)
    const int wn = warp & 1;             // 0..1 (N, 64 cols each)
    const int mb = blockIdx.x * 256;
    const int nb = blockIdx.y * 128;

    const float* Wp;
    int nloc;
    if (MODE == 0) {
        int w = nb >> 10;
        Wp = (w == 0) ? W0 : ((w == 1) ? W1 : W2);
        nloc = nb & 1023;
    } else {
        Wp = W0;
        nloc = nb;
    }

    const int lrow = tid >> 3;           // base row (step 32)
    const int lkq  = (tid & 7) << 2;     // k offset (4 elements)

    float4 stB[4];
    float4 stA[8];                       // MODE 0 (fp32 A, 256 rows)
    uint2  stAh[8];                      // MODE 1 (fp16 A)

    // ---- prologue fill (stage 0) ----
#pragma unroll
    for (int i = 0; i < 8; i++) {
        int row = lrow + 32 * i;
        if (MODE == 0)
            stA[i] = *(const float4*)(A_ + (size_t)(mb + row) * 1024 + lkq);
        else
            stAh[i] = *(const uint2*)(g_attnh + (size_t)(mb + row) * 1024 + lkq);
    }
#pragma unroll
    for (int i = 0; i < 4; i++) {
        int row = lrow + 32 * i;
        stB[i] = *(const float4*)(Wp + (size_t)(nloc + row) * 1024 + lkq);
    }
    {
        __half* As = gsmh;
        __half* Bs = gsmh + ABUF_H;
#pragma unroll
        for (int i = 0; i < 8; i++) {
            int row = lrow + 32 * i;
            if (MODE == 0)
                *(uint2*)&As[row * LDH + lkq] =
                    make_uint2(pack_h2(stA[i].x, stA[i].y), pack_h2(stA[i].z, stA[i].w));
            else
                *(uint2*)&As[row * LDH + lkq] = stAh[i];
        }
#pragma unroll
        for (int i = 0; i < 4; i++) {
            int row = lrow + 32 * i;
            *(uint2*)&Bs[row * LDH + lkq] =
                make_uint2(pack_h2(stB[i].x, stB[i].y), pack_h2(stB[i].z, stB[i].w));
        }
    }
    __syncthreads();

    float c[4][8][4];
#pragma unroll
    for (int i = 0; i < 4; i++)
#pragma unroll
        for (int nt = 0; nt < 8; nt++)
#pragma unroll
            for (int e = 0; e < 4; e++) c[i][nt][e] = 0.f;

    for (int kt = 0; kt < 32; kt++) {
        if (kt + 1 < 32) {
            int kb = (kt + 1) * 32;
#pragma unroll
            for (int i = 0; i < 8; i++) {
                int row = lrow + 32 * i;
                if (MODE == 0)
                    stA[i] = *(const float4*)(A_ + (size_t)(mb + row) * 1024 + kb + lkq);
                else
                    stAh[i] = *(const uint2*)(g_attnh + (size_t)(mb + row) * 1024 + kb + lkq);
            }
#pragma unroll
            for (int i = 0; i < 4; i++) {
                int row = lrow + 32 * i;
                stB[i] = *(const float4*)(Wp + (size_t)(nloc + row) * 1024 + kb + lkq);
            }
        }

        const uint32_t* As_u = (const uint32_t*)(gsmh + (kt & 1) * STAGE_H);
        const uint32_t* Bs_u = As_u + ABUF_H / 2;

#pragma unroll
        for (int k0 = 0; k0 < 2; k0++) {            // k0h = 0, 8 (uint units)
            const int k0h = k0 * 8;
            uint32_t af[4][4];
#pragma unroll
            for (int i = 0; i < 4; i++) {
                int m0 = wm * 64 + i * 16;
                af[i][0] = As_u[(m0 + g)     * (LDH / 2) + k0h + t];
                af[i][1] = As_u[(m0 + g + 8) * (LDH / 2) + k0h + t];
                af[i][2] = As_u[(m0 + g)     * (LDH / 2) + k0h + 4 + t];
                af[i][3] = As_u[(m0 + g + 8) * (LDH / 2) + k0h + 4 + t];
            }
#pragma unroll
            for (int nt = 0; nt < 8; nt++) {
                int n0 = wn * 64 + nt * 8;
                uint32_t b0 = Bs_u[(n0 + g) * (LDH / 2) + k0h + t];
                uint32_t b1 = Bs_u[(n0 + g) * (LDH / 2) + k0h + 4 + t];
                mma_f16(c[0][nt], af[0], b0, b1);
                mma_f16(c[1][nt], af[1], b0, b1);
                mma_f16(c[2][nt], af[2], b0, b1);
                mma_f16(c[3][nt], af[3], b0, b1);
            }
        }

        if (kt + 1 < 32) {
            __half* Asn = gsmh + ((kt + 1) & 1) * STAGE_H;
            __half* Bsn = Asn + ABUF_H;
#pragma unroll
            for (int i = 0; i < 8; i++) {
                int row = lrow + 32 * i;
                if (MODE == 0)
                    *(uint2*)&Asn[row * LDH + lkq] =
                        make_uint2(pack_h2(stA[i].x, stA[i].y), pack_h2(stA[i].z, stA[i].w));
                else
                    *(uint2*)&Asn[row * LDH + lkq] = stAh[i];
            }
#pragma unroll
            for (int i = 0; i < 4; i++) {
                int row = lrow + 32 * i;
                *(uint2*)&Bsn[row * LDH + lkq] =
                    make_uint2(pack_h2(stB[i].x, stB[i].y), pack_h2(stB[i].z, stB[i].w));
            }
            __syncthreads();
        }
    }

    // ---- epilogue (MODE 0: fused RoPE on q/k; V transposed) ----
    const float SCALE = 0.125f * 1.4426950408889634f;
#pragma unroll
    for (int i = 0; i < 4; i++) {
        int m0 = mb + wm * 64 + i * 16;
        int r0 = m0 + g, r1 = m0 + g + 8;
#pragma unroll
        for (int nt = 0; nt < 8; nt++) {
            int ncg = nb + wn * 64 + nt * 8 + 2 * t;
            float c0 = c[i][nt][0], c1 = c[i][nt][1];
            float c2 = c[i][nt][2], c3 = c[i][nt][3];
            if (MODE == 0) {
                int w = ncg >> 10;
                int hn = ncg & 1023;
                int hh = hn >> 6, dd = hn & 63;        // dd even
                int bi0 = r0 >> 11, t0 = r0 & 2047;
                int bi1 = r1 >> 11, t1 = r1 & 2047;
                if (w < 2) {
                    int j = dd >> 1;
                    float cs0 = g_cos[t0 * 32 + j], sn0 = g_sin[t0 * 32 + j];
                    float cs1 = g_cos[t1 * 32 + j], sn1 = g_sin[t1 * 32 + j];
                    float o00 = cs0 * c0 - sn0 * c1;
                    float o01 = sn0 * c0 + cs0 * c1;
                    float o10 = cs1 * c2 - sn1 * c3;
                    float o11 = sn1 * c2 + cs1 * c3;
                    if (w == 0) { o00 *= SCALE; o01 *= SCALE; o10 *= SCALE; o11 *= SCALE; }
                    __half* dst = (w == 0) ? g_qh : g_kh;
                    *(__half2*)&dst[((size_t)(bi0 * NH + hh) * TT + t0) * DK + dd] =
                        __floats2half2_rn(o00, o01);
                    *(__half2*)&dst[((size_t)(bi1 * NH + hh) * TT + t1) * DK + dd] =
                        __floats2half2_rn(o10, o11);
                } else {
                    size_t b0i = ((size_t)(bi0 * NH + hh) * DK + dd) * TT + t0;
                    g_vh[b0i]      = __float2half_rn(c0);
                    g_vh[b0i + TT] = __float2half_rn(c1);
                    size_t b1i = ((size_t)(bi1 * NH + hh) * DK + dd) * TT + t1;
                    g_vh[b1i]      = __float2half_rn(c2);
                    g_vh[b1i + TT] = __float2half_rn(c3);
                }
            } else {
                *(float2*)&Cout[(size_t)r0 * DMODEL + ncg] = make_float2(c0, c1);
                *(float2*)&Cout[(size_t)r1 * DMODEL + ncg] = make_float2(c2, c3);
            }
        }
    }
}

// ---------------------------------------------------------------------------
// Flash attention, fp16 m16n8k16 (R13-proven, unchanged). qt descending;
// output fp16 into g_attnh.
// smem: Ks[64][72] halfs ([c][d]), Vt[64][72] halfs ([d][c]).
// ---------------------------------------------------------------------------
#define LDKH 72
#define FLASH_SMEM (2 * 64 * LDKH * 2)

__global__ void __launch_bounds__(256, 2) flash_mma_kernel() {
    extern __shared__ __half fsh[];
    __half* Ks = fsh;                   // [c][d]
    __half* Vt = fsh + 64 * LDKH;       // [d][c]

    const int qt = (gridDim.x - 1) - blockIdx.x;
    const int h  = blockIdx.y;
    const int bz = blockIdx.z;
    const int tid = threadIdx.x;
    const int lane = tid & 31;
    const int w = tid >> 5;
    const int g = lane >> 2;
    const int t = lane & 3;

    const size_t head_off = (size_t)(bz * NH + h) * TT * DK;
    const int rbase = qt * 128 + w * 16;

    const __half* kbase = g_kh + head_off;
    const __half* vbase = g_vh + (size_t)(bz * NH + h) * DK * TT;

    uint32_t qf[4][4];
    {
        const __half* qp = g_qh + head_off + (size_t)rbase * DK;
#pragma unroll
        for (int kc = 0; kc < 4; kc++) {
            qf[kc][0] = *(const uint32_t*)&qp[(size_t)g * DK + 16 * kc + 2 * t];
            qf[kc][1] = *(const uint32_t*)&qp[(size_t)(g + 8) * DK + 16 * kc + 2 * t];
            qf[kc][2] = *(const uint32_t*)&qp[(size_t)g * DK + 16 * kc + 8 + 2 * t];
            qf[kc][3] = *(const uint32_t*)&qp[(size_t)(g + 8) * DK + 16 * kc + 8 + 2 * t];
        }
    }

    float oa[8][4];
#pragma unroll
    for (int i = 0; i < 8; i++)
#pragma unroll
        for (int j = 0; j < 4; j++) oa[i][j] = 0.f;
    float m0 = -1e30f, m1 = -1e30f, l0 = 0.f, l1 = 0.f;

    const int ktiles = 2 * qt + 2;
    for (int j = 0; j < ktiles; j++) {
        __syncthreads();
        {
            const __half* kp = kbase + (size_t)j * 64 * DK;
            const __half* vp = vbase + 64 * j;
#pragma unroll
            for (int i = 0; i < 2; i++) {
                int f8 = tid + 256 * i;
                int r = f8 >> 3, cq = (f8 & 7) * 8;
                *(uint4*)&Ks[r * LDKH + cq] = *(const uint4*)(kp + r * DK + cq);
                *(uint4*)&Vt[r * LDKH + cq] = *(const uint4*)(vp + (size_t)r * TT + cq);
            }
        }
        __syncthreads();

        if (64 * j > rbase + 15) continue;

        const uint32_t* Ks_u = (const uint32_t*)Ks;
        const uint32_t* Vt_u = (const uint32_t*)Vt;

        float sa[8][4];
#pragma unroll
        for (int nt = 0; nt < 8; nt++) {
            sa[nt][0] = sa[nt][1] = sa[nt][2] = sa[nt][3] = 0.f;
#pragma unroll
            for (int kc = 0; kc < 4; kc++) {
                uint32_t b0 = Ks_u[(8 * nt + g) * (LDKH / 2) + 8 * kc + t];
                uint32_t b1 = Ks_u[(8 * nt + g) * (LDKH / 2) + 8 * kc + 4 + t];
                mma_f16(sa[nt], qf[kc], b0, b1);
            }
        }

        if (64 * j + 63 > rbase) {
            const int r0 = rbase + g, r1 = rbase + g + 8;
#pragma unroll
            for (int nt = 0; nt < 8; nt++) {
                int c0 = 64 * j + 8 * nt + 2 * t;
                if (c0 > r0)     sa[nt][0] = -1e30f;
                if (c0 + 1 > r0) sa[nt][1] = -1e30f;
                if (c0 > r1)     sa[nt][2] = -1e30f;
                if (c0 + 1 > r1) sa[nt][3] = -1e30f;
            }
        }

        float mx0 = -1e30f, mx1 = -1e30f;
#pragma unroll
        for (int nt = 0; nt < 8; nt++) {
            mx0 = fmaxf(mx0, fmaxf(sa[nt][0], sa[nt][1]));
            mx1 = fmaxf(mx1, fmaxf(sa[nt][2], sa[nt][3]));
        }
        mx0 = fmaxf(mx0, __shfl_xor_sync(0xffffffffu, mx0, 1));
        mx0 = fmaxf(mx0, __shfl_xor_sync(0xffffffffu, mx0, 2));
        mx1 = fmaxf(mx1, __shfl_xor_sync(0xffffffffu, mx1, 1));
        mx1 = fmaxf(mx1, __shfl_xor_sync(0xffffffffu, mx1, 2));
        float mn0 = fmaxf(m0, mx0), mn1 = fmaxf(m1, mx1);
        float al0 = exp2f(m0 - mn0), al1 = exp2f(m1 - mn1);
        m0 = mn0; m1 = mn1;

        float sum0 = 0.f, sum1 = 0.f;
#pragma unroll
        for (int nt = 0; nt < 8; nt++) {
            float p0 = exp2f(sa[nt][0] - mn0);
            float p1 = exp2f(sa[nt][1] - mn0);
            float p2 = exp2f(sa[nt][2] - mn1);
            float p3 = exp2f(sa[nt][3] - mn1);
            sum0 += p0 + p1;
            sum1 += p2 + p3;
            sa[nt][0] = p0; sa[nt][1] = p1; sa[nt][2] = p2; sa[nt][3] = p3;
        }
        sum0 += __shfl_xor_sync(0xffffffffu, sum0, 1);
        sum0 += __shfl_xor_sync(0xffffffffu, sum0, 2);
        sum1 += __shfl_xor_sync(0xffffffffu, sum1, 1);
        sum1 += __shfl_xor_sync(0xffffffffu, sum1, 2);
        l0 = l0 * al0 + sum0;
        l1 = l1 * al1 + sum1;

#pragma unroll
        for (int dt = 0; dt < 8; dt++) {
            oa[dt][0] *= al0; oa[dt][1] *= al0;
            oa[dt][2] *= al1; oa[dt][3] *= al1;
        }

        uint32_t pf[4][4];
#pragma unroll
        for (int kc = 0; kc < 4; kc++) {
            pf[kc][0] = pack_h2(sa[2 * kc][0],     sa[2 * kc][1]);
            pf[kc][1] = pack_h2(sa[2 * kc][2],     sa[2 * kc][3]);
            pf[kc][2] = pack_h2(sa[2 * kc + 1][0], sa[2 * kc + 1][1]);
            pf[kc][3] = pack_h2(sa[2 * kc + 1][2], sa[2 * kc + 1][3]);
        }

#pragma unroll
        for (int kc = 0; kc < 4; kc++) {
#pragma unroll
            for (int dt = 0; dt < 8; dt++) {
                uint32_t b0 = Vt_u[(8 * dt + g) * (LDKH / 2) + 8 * kc + t];
                uint32_t b1 = Vt_u[(8 * dt + g) * (LDKH / 2) + 8 * kc + 4 + t];
                mma_f16(oa[dt], pf[kc], b0, b1);
            }
        }
    }

    {
        float inv0 = 1.f / l0, inv1 = 1.f / l1;
        __half* op0 = g_attnh + (size_t)(bz * TT + rbase + g) * DMODEL + h * DK;
        __half* op1 = g_attnh + (size_t)(bz * TT + rbase + g + 8) * DMODEL + h * DK;
#pragma unroll
        for (int dt = 0; dt < 8; dt++) {
            *(uint32_t*)&op0[8 * dt + 2 * t] = pack_h2(oa[dt][0] * inv0, oa[dt][1] * inv0);
            *(uint32_t*)&op1[8 * dt + 2 * t] = pack_h2(oa[dt][2] * inv1, oa[dt][3] * inv1);
        }
    }
}

// ---------------------------------------------------------------------------
extern "C" void kernel_launch(void* const* d_in, const int* in_sizes, int n_in,
                              void* d_out, int out_size) {
    (void)in_sizes; (void)n_in; (void)out_size;
    const float* x  = (const float*)d_in[0];
    const float* Wq = (const float*)d_in[2];
    const float* Wk = (const float*)d_in[3];
    const float* Wv = (const float*)d_in[4];
    const float* Wo = (const float*)d_in[5];
    float* out = (float*)d_out;

    cudaFuncSetAttribute(flash_mma_kernel,
                         cudaFuncAttributeMaxDynamicSharedMemorySize, FLASH_SMEM);
    cudaFuncSetAttribute(gemm_mma_kernel<0>,
                         cudaFuncAttributeMaxDynamicSharedMemorySize, GEMM_SMEM);
    cudaFuncSetAttribute(gemm_mma_kernel<1>,
                         cudaFuncAttributeMaxDynamicSharedMemorySize, GEMM_SMEM);

    rope_table_kernel<<<(TT * 32 + 255) / 256, 256>>>();

    gemm_mma_kernel<0><<<dim3(MROWS / 256, 3072 / 128), 256, GEMM_SMEM>>>(
        x, Wq, Wk, Wv, nullptr);

    flash_mma_kernel<<<dim3(TT / 128, NH, BB), 256, FLASH_SMEM>>>();

    gemm_mma_kernel<1><<<dim3(MROWS / 256, DMODEL / 128), 256, GEMM_SMEM>>>(
        nullptr, Wo, nullptr, nullptr, out);
}